// round 6
// baseline (speedup 1.0000x reference)
#include <cuda_runtime.h>
#include <cuda_bf16.h>
#include <cstdint>

// Problem constants (SAGEEncoder: N=50000, E=800000, IN=128, HID=128, OUT=64)
#define NMAX 50000
#define EMAX 800000
#define D_IN 128
#define D_HID 128
#define D_OUT 64

#define SCAN_TILE 512
#define SCAN_NBLK ((NMAX + SCAN_TILE - 1) / SCAN_TILE)   // 98

// ---------------- scratch (static device globals; no allocation) -------------
__device__ __align__(16) int   g_deg[NMAX];
__device__ __align__(16) int   g_rowstart[NMAX + 1];
__device__ __align__(16) int   g_cursor[NMAX];
__device__ __align__(16) int   g_csr[EMAX];
__device__ __align__(16) int   g_tilesum[SCAN_NBLK];
__device__ __align__(16) int   g_tileoff[SCAN_NBLK];
__device__ __align__(16) float g_t1[(size_t)NMAX * 256]; // [n][0:128)=feat@Wself1, [128:256)=feat@Wneigh1
__device__ __align__(16) float g_h1[(size_t)NMAX * 128]; // relu'd layer-1 output
__device__ __align__(16) float g_t2[(size_t)NMAX * 128]; // [n][0:64)=h1@Wself2, [64:128)=h1@Wneigh2
__device__ int g_is64;

// ---------------- index dtype detection --------------------------------------
__global__ void detect_kernel(const int* __restrict__ idx32, int E) {
    __shared__ int nz;
    if (threadIdx.x == 0) nz = 0;
    __syncthreads();
    int i = threadIdx.x;
    if (idx32[2 * i + 1] != 0) atomicAdd(&nz, 1);
    __syncthreads();
    if (threadIdx.x == 0) g_is64 = (nz == 0) ? 1 : 0;
}

__device__ __forceinline__ int load_idx(const void* p, int e, int is64) {
    if (is64) return (int)((const long long*)p)[e];
    return ((const int*)p)[e];
}

// ---------------- CSR build --------------------------------------------------
__global__ void zero_deg_kernel(int n) {
    int i = blockIdx.x * blockDim.x + threadIdx.x;
    if (i < n) g_deg[i] = 0;
}

__global__ void hist_kernel(const void* __restrict__ dst, int E) {
    int is64 = g_is64;
    for (int e = blockIdx.x * blockDim.x + threadIdx.x; e < E; e += gridDim.x * blockDim.x)
        atomicAdd(&g_deg[load_idx(dst, e, is64)], 1);
}

__global__ void scanA_kernel(int n) {
    __shared__ int red[SCAN_TILE];
    int t = threadIdx.x;
    int i = blockIdx.x * SCAN_TILE + t;
    red[t] = (i < n) ? g_deg[i] : 0;
    __syncthreads();
    for (int off = SCAN_TILE / 2; off > 0; off >>= 1) {
        if (t < off) red[t] += red[t + off];
        __syncthreads();
    }
    if (t == 0) g_tilesum[blockIdx.x] = red[0];
}

__global__ void scanB_kernel() {
    __shared__ int s[128];
    int t = threadIdx.x;
    s[t] = (t < SCAN_NBLK) ? g_tilesum[t] : 0;
    __syncthreads();
    for (int off = 1; off < 128; off <<= 1) {
        int v = (t >= off) ? s[t - off] : 0;
        __syncthreads();
        s[t] += v;
        __syncthreads();
    }
    if (t < SCAN_NBLK) g_tileoff[t] = (t == 0) ? 0 : s[t - 1];
}

__global__ void scanC_kernel(int n, int E) {
    __shared__ int s[SCAN_TILE];
    int t = threadIdx.x;
    int i = blockIdx.x * SCAN_TILE + t;
    int v = (i < n) ? g_deg[i] : 0;
    s[t] = v;
    __syncthreads();
    for (int off = 1; off < SCAN_TILE; off <<= 1) {
        int u = (t >= off) ? s[t - off] : 0;
        __syncthreads();
        s[t] += u;
        __syncthreads();
    }
    if (i < n) {
        int excl = g_tileoff[blockIdx.x] + s[t] - v;
        g_rowstart[i] = excl;
        g_cursor[i]   = excl;
        if (i == n - 1) g_rowstart[n] = E;
    }
}

__global__ void scatter_kernel(const void* __restrict__ src,
                               const void* __restrict__ dst, int E) {
    int is64 = g_is64;
    for (int e = blockIdx.x * blockDim.x + threadIdx.x; e < E; e += gridDim.x * blockDim.x) {
        int d = load_idx(dst, e, is64);
        int pos = atomicAdd(&g_cursor[d], 1);
        g_csr[pos] = load_idx(src, e, is64);
    }
}

// ---------------- tf32-split tensor-core dual GEMM ---------------------------
// C[M x 2*halfN] = A[M x K] @ [W0 | W1] using mma.m16n8k8 tf32, 3-term split.
#define TBM 128
#define TBN 128
#define TBK 32
#define APAD 8
#define ASTR (TBM + APAD)
#define WSTR (TBN + APAD)

__device__ __forceinline__ uint32_t f2tf(float x) {
    uint32_t r;
    asm("cvt.rna.tf32.f32 %0, %1;" : "=r"(r) : "f"(x));
    return r;
}

__device__ __forceinline__ void mma_tf32(float* c, uint32_t a0, uint32_t a1,
                                         uint32_t a2, uint32_t a3,
                                         uint32_t b0, uint32_t b1) {
    asm volatile(
        "mma.sync.aligned.m16n8k8.row.col.f32.tf32.tf32.f32 "
        "{%0,%1,%2,%3}, {%4,%5,%6,%7}, {%8,%9}, {%0,%1,%2,%3};"
        : "+f"(c[0]), "+f"(c[1]), "+f"(c[2]), "+f"(c[3])
        : "r"(a0), "r"(a1), "r"(a2), "r"(a3), "r"(b0), "r"(b1));
}

__global__ __launch_bounds__(256) void gemm_tf32_kernel(
    const float* __restrict__ Aext,
    const float* __restrict__ W0,
    const float* __restrict__ W1,
    int M, int K, int halfN, int layer)
{
    const float* __restrict__ A = (layer == 1) ? Aext : g_h1;
    float* __restrict__ C       = (layer == 1) ? g_t1 : g_t2;

    const int N  = 2 * halfN;
    const int bn = blockIdx.x * TBN;
    const int bm = blockIdx.y * TBM;

    __shared__ float As[TBK][ASTR];   // transposed A tile: As[k][row]
    __shared__ float Ws[TBK][WSTR];   // Ws[k][col]

    const int tid  = threadIdx.x;
    const int lane = tid & 31;
    const int warp = tid >> 5;
    const int wm = warp >> 1;
    const int wn = warp & 1;

    const int arow  = tid >> 1;
    const int akb   = (tid & 1) * 16;
    const int aValid = (bm + arow < M);
    const int bkr   = tid >> 3;
    const int bcb   = (tid & 7) * 16;
    const int gcol0 = bn + bcb;
    const float* __restrict__ Wp = (gcol0 < halfN) ? W0 : W1;
    const int wc = (gcol0 < halfN) ? gcol0 : gcol0 - halfN;

    float acc[2][8][4];
#pragma unroll
    for (int i = 0; i < 2; i++)
#pragma unroll
        for (int j = 0; j < 8; j++)
#pragma unroll
            for (int q = 0; q < 4; q++) acc[i][j][q] = 0.f;

    for (int k0 = 0; k0 < K; k0 += TBK) {
#pragma unroll
        for (int v = 0; v < 4; v++) {
            float4 av = make_float4(0.f, 0.f, 0.f, 0.f);
            if (aValid)
                av = *reinterpret_cast<const float4*>(
                    &A[(size_t)(bm + arow) * K + k0 + akb + v * 4]);
            As[akb + v * 4 + 0][arow] = av.x;
            As[akb + v * 4 + 1][arow] = av.y;
            As[akb + v * 4 + 2][arow] = av.z;
            As[akb + v * 4 + 3][arow] = av.w;
        }
#pragma unroll
        for (int v = 0; v < 4; v++) {
            float4 bv = *reinterpret_cast<const float4*>(
                &Wp[(size_t)(k0 + bkr) * halfN + wc + v * 4]);
            *reinterpret_cast<float4*>(&Ws[bkr][bcb + v * 4]) = bv;
        }
        __syncthreads();

#pragma unroll
        for (int ks = 0; ks < TBK / 8; ks++) {
            const int kb = ks * 8;
            uint32_t bhi[8][2], blo[8][2];
#pragma unroll
            for (int nj = 0; nj < 8; nj++) {
                int c = wn * 64 + nj * 8 + (lane >> 2);
                float b0 = Ws[kb + (lane & 3)][c];
                float b1 = Ws[kb + 4 + (lane & 3)][c];
                bhi[nj][0] = f2tf(b0);
                blo[nj][0] = f2tf(b0 - __uint_as_float(bhi[nj][0]));
                bhi[nj][1] = f2tf(b1);
                blo[nj][1] = f2tf(b1 - __uint_as_float(bhi[nj][1]));
            }
#pragma unroll
            for (int mi = 0; mi < 2; mi++) {
                int r = wm * 32 + mi * 16 + (lane >> 2);
                float a0 = As[kb + (lane & 3)][r];
                float a1 = As[kb + (lane & 3)][r + 8];
                float a2 = As[kb + 4 + (lane & 3)][r];
                float a3 = As[kb + 4 + (lane & 3)][r + 8];
                uint32_t ah0 = f2tf(a0), ah1 = f2tf(a1), ah2 = f2tf(a2), ah3 = f2tf(a3);
                uint32_t al0 = f2tf(a0 - __uint_as_float(ah0));
                uint32_t al1 = f2tf(a1 - __uint_as_float(ah1));
                uint32_t al2 = f2tf(a2 - __uint_as_float(ah2));
                uint32_t al3 = f2tf(a3 - __uint_as_float(ah3));
#pragma unroll
                for (int nj = 0; nj < 8; nj++) {
                    mma_tf32(acc[mi][nj], ah0, ah1, ah2, ah3, bhi[nj][0], bhi[nj][1]);
                    mma_tf32(acc[mi][nj], ah0, ah1, ah2, ah3, blo[nj][0], blo[nj][1]);
                    mma_tf32(acc[mi][nj], al0, al1, al2, al3, bhi[nj][0], bhi[nj][1]);
                }
            }
        }
        __syncthreads();
    }

#pragma unroll
    for (int mi = 0; mi < 2; mi++) {
        int r0 = bm + wm * 32 + mi * 16 + (lane >> 2);
#pragma unroll
        for (int nj = 0; nj < 8; nj++) {
            int col = bn + wn * 64 + nj * 8 + (lane & 3) * 2;
            if (r0 < M)
                *reinterpret_cast<float2*>(&C[(size_t)r0 * N + col]) =
                    make_float2(acc[mi][nj][0], acc[mi][nj][1]);
            if (r0 + 8 < M)
                *reinterpret_cast<float2*>(&C[(size_t)(r0 + 8) * N + col]) =
                    make_float2(acc[mi][nj][2], acc[mi][nj][3]);
        }
    }
}

// ---------------- aggregation + epilogue (4-way MLP unroll) ------------------
__global__ void agg_epilogue1_kernel(const float* __restrict__ b1, int n) {
    int node = blockIdx.x * blockDim.y + threadIdx.y;
    if (node >= n) return;
    int j = threadIdx.x;   // 0..127
    int beg = g_rowstart[node];
    int end = g_rowstart[node + 1];
    float acc = 0.f;
    int e = beg;
    for (; e + 4 <= end; e += 4) {
        int s0 = g_csr[e], s1 = g_csr[e + 1], s2 = g_csr[e + 2], s3 = g_csr[e + 3];
        float v0 = g_t1[(size_t)s0 * 256 + 128 + j];
        float v1 = g_t1[(size_t)s1 * 256 + 128 + j];
        float v2 = g_t1[(size_t)s2 * 256 + 128 + j];
        float v3 = g_t1[(size_t)s3 * 256 + 128 + j];
        acc += (v0 + v1) + (v2 + v3);
    }
    for (; e < end; e++)
        acc += g_t1[(size_t)g_csr[e] * 256 + 128 + j];
    float inv = 1.f / fmaxf((float)(end - beg), 1.f);
    float v = g_t1[(size_t)node * 256 + j] + acc * inv + b1[j];
    g_h1[(size_t)node * 128 + j] = fmaxf(v, 0.f);
}

__global__ void agg_epilogue2_kernel(const float* __restrict__ b2,
                                     float* __restrict__ out, int n) {
    int node = blockIdx.x * blockDim.y + threadIdx.y;
    if (node >= n) return;
    int j = threadIdx.x;   // 0..63
    int beg = g_rowstart[node];
    int end = g_rowstart[node + 1];
    float acc = 0.f;
    int e = beg;
    for (; e + 4 <= end; e += 4) {
        int s0 = g_csr[e], s1 = g_csr[e + 1], s2 = g_csr[e + 2], s3 = g_csr[e + 3];
        float v0 = g_t2[(size_t)s0 * 128 + 64 + j];
        float v1 = g_t2[(size_t)s1 * 128 + 64 + j];
        float v2 = g_t2[(size_t)s2 * 128 + 64 + j];
        float v3 = g_t2[(size_t)s3 * 128 + 64 + j];
        acc += (v0 + v1) + (v2 + v3);
    }
    for (; e < end; e++)
        acc += g_t2[(size_t)g_csr[e] * 128 + 64 + j];
    float inv = 1.f / fmaxf((float)(end - beg), 1.f);
    out[(size_t)node * 64 + j] = g_t2[(size_t)node * 128 + j] + acc * inv + b2[j];
}

// ---------------- launch -----------------------------------------------------
extern "C" void kernel_launch(void* const* d_in, const int* in_sizes, int n_in,
                              void* d_out, int out_size) {
    const float* feat     = (const float*)d_in[0];
    const void*  src      = d_in[1];
    const void*  dst      = d_in[2];
    const float* W_self1  = (const float*)d_in[3];
    const float* W_neigh1 = (const float*)d_in[4];
    const float* b1       = (const float*)d_in[5];
    const float* W_self2  = (const float*)d_in[6];
    const float* W_neigh2 = (const float*)d_in[7];
    const float* b2       = (const float*)d_in[8];
    float* out = (float*)d_out;

    const int N = in_sizes[0] / D_IN;   // 50000
    const int E = in_sizes[1];          // 800000

    // ---- fork a side stream: CSR build runs parallel to GEMM1 in the graph
    cudaStream_t s_csr;
    cudaEvent_t evFork, evJoin;
    cudaStreamCreateWithFlags(&s_csr, cudaStreamNonBlocking);
    cudaEventCreateWithFlags(&evFork, cudaEventDisableTiming);
    cudaEventCreateWithFlags(&evJoin, cudaEventDisableTiming);

    cudaEventRecord(evFork, 0);
    cudaStreamWaitEvent(s_csr, evFork, 0);

    // ---- CSR branch (side stream)
    detect_kernel<<<1, 256, 0, s_csr>>>((const int*)dst, E);
    zero_deg_kernel<<<(N + 255) / 256, 256, 0, s_csr>>>(N);
    hist_kernel<<<2048, 256, 0, s_csr>>>(dst, E);
    scanA_kernel<<<SCAN_NBLK, SCAN_TILE, 0, s_csr>>>(N);
    scanB_kernel<<<1, 128, 0, s_csr>>>();
    scanC_kernel<<<SCAN_NBLK, SCAN_TILE, 0, s_csr>>>(N, E);
    scatter_kernel<<<2048, 256, 0, s_csr>>>(src, dst, E);
    cudaEventRecord(evJoin, s_csr);

    // ---- GEMM1 branch (main stream): feat @ [W_self1 | W_neigh1] -> g_t1
    {
        dim3 grid(256 / TBN, (N + TBM - 1) / TBM);
        gemm_tf32_kernel<<<grid, 256>>>(feat, W_self1, W_neigh1, N, D_IN, D_HID, 1);
    }

    // ---- join: agg1 needs both CSR and t1
    cudaStreamWaitEvent(0, evJoin, 0);
    {
        dim3 block(128, 2);
        agg_epilogue1_kernel<<<(N + 1) / 2, block>>>(b1, N);
    }

    // ---- layer 2
    {
        dim3 grid(128 / TBN, (N + TBM - 1) / TBM);
        gemm_tf32_kernel<<<grid, 256>>>(feat, W_self2, W_neigh2, N, D_HID, D_OUT, 2);
    }
    {
        dim3 block(64, 4);
        agg_epilogue2_kernel<<<(N + 3) / 4, block>>>(b2, out, N);
    }

    cudaEventDestroy(evFork);
    cudaEventDestroy(evJoin);
    cudaStreamDestroy(s_csr);
}